// round 6
// baseline (speedup 1.0000x reference)
#include <cuda_runtime.h>
#include <cstdint>

#define N_NODES 2048
#define N_EDGES 8192
#define EDGE_DIM 10
#define EH 32
#define HID 160
#define COL_B2 (EH*HID)              // 5120
#define COL_ROOT (EH*HID + HID)      // 5280
#define NCOLS (EH*HID + HID + HID)   // 5440

// k-permutation within 8-blocks: orig k%8 = t(0..3) -> 2t ; t+4 -> 2t+1
__host__ __device__ __forceinline__ int kpos(int k) {
    return (k & ~7) | ((k & 3) << 1) | ((k & 4) >> 2);
}

// ---------------- device scratch ----------------
__device__ float g_T[N_NODES * NCOLS];    // tf32 bits, cols kpos-permuted
__device__ float g_B[2][NCOLS * HID];     // tf32 bits, rows kpos-permuted
__device__ float g_h[2][N_EDGES * EH];
__device__ float g_out[N_NODES * HID];    // split-K accumulator (fp32)
__device__ float g_xb[2][N_NODES * HID];  // layer ping-pong (fp32)
__device__ int   g_src[N_EDGES];
__device__ int   g_csr_off[N_NODES + 1];  // CSR by dst
__device__ int   g_csr_edge[N_EDGES];

__device__ __forceinline__ uint32_t f2tf32(float f) {
    uint32_t u;
    asm("cvt.rna.tf32.f32 %0, %1;" : "=r"(u) : "f"(f));
    return u;
}

// =====================================================================
// Preprocessing (one block): int64-detect, decode, CSR by dst.
// =====================================================================
__global__ __launch_bounds__(1024) void prep_kernel(const void* __restrict__ eiraw) {
    __shared__ int s_flag;
    __shared__ int s_cd[N_NODES];
    __shared__ int s_a[N_NODES];
    __shared__ int s_b[N_NODES];
    int t = threadIdx.x;

    for (int i = t; i < N_NODES; i += 1024) s_cd[i] = 0;
    if (t == 0) s_flag = 0;
    __syncthreads();

    const int* raw = (const int*)eiraw;
    int f = 0;
    for (int i = t; i < N_EDGES; i += 1024)
        if (raw[2 * i + 1] != 0) f = 1;
    if (f) atomicOr(&s_flag, 1);
    __syncthreads();
    int flag = s_flag;

    int es[8], ed[8];
    #pragma unroll
    for (int j = 0; j < 8; j++) {
        int e = t + 1024 * j;
        if (flag) {
            es[j] = raw[e]; ed[j] = raw[N_EDGES + e];
        } else {
            const long long* p = (const long long*)eiraw;
            es[j] = (int)p[e]; ed[j] = (int)p[N_EDGES + e];
        }
        atomicAdd(&s_cd[ed[j]], 1);
        g_src[e] = es[j];
    }
    __syncthreads();

    for (int i = t; i < N_NODES; i += 1024) s_a[i] = s_cd[i];
    __syncthreads();

    int* pa = s_a; int* pb = s_b;
    for (int d = 1; d < N_NODES; d <<= 1) {
        for (int i = t; i < N_NODES; i += 1024)
            pb[i] = pa[i] + (i >= d ? pa[i - d] : 0);
        __syncthreads();
        int* tmp = pa; pa = pb; pb = tmp;
    }
    for (int i = t; i < N_NODES; i += 1024) {
        int off = (i == 0) ? 0 : pa[i - 1];
        g_csr_off[i] = off;
        pb[i] = off;
    }
    if (t == 0) g_csr_off[N_NODES] = N_EDGES;
    __syncthreads();

    #pragma unroll
    for (int j = 0; j < 8; j++) {
        int e = t + 1024 * j;
        int pos = atomicAdd(&pb[ed[j]], 1);
        g_csr_edge[pos] = e;
    }
}

// =====================================================================
// Params: build g_B (tf32, row-permuted) for both slots + edge MLP h
// (both slots) + zero g_out.
// =====================================================================
#define GB_BLOCKS (NCOLS * HID / 256)                // 3400
#define H_BLOCKS  (N_EDGES / 8)                      // 1024
#define Z_BLOCKS  (N_NODES * HID / 256)              // 1280

__global__ __launch_bounds__(256) void params_kernel(
        const float* __restrict__ w2a, const float* __restrict__ b2a,
        const float* __restrict__ roota,
        const float* __restrict__ w2b, const float* __restrict__ b2b,
        const float* __restrict__ rootb,
        const float* __restrict__ ea,
        const float* __restrict__ w1a, const float* __restrict__ b1a,
        const float* __restrict__ w1b, const float* __restrict__ b1b) {
    __shared__ float sw[EDGE_DIM * EH];
    __shared__ float sb[EH];
    int b = blockIdx.x;
    int t = threadIdx.x;

    if (b < 2 * GB_BLOCKS) {
        int slot = (b >= GB_BLOCKS);
        const float* w2   = slot ? w2b : w2a;
        const float* b2   = slot ? b2b : b2a;
        const float* root = slot ? rootb : roota;
        int idx = (b - slot * GB_BLOCKS) * 256 + t;   // < 870400
        int c = idx / HID;
        int o = idx % HID;
        float v;
        if (c < COL_B2)         v = w2[c * HID + o];          // w2 flat IS [5120,160]
        else if (c < COL_ROOT)  v = b2[(c - COL_B2) * HID + o];
        else                    v = root[(c - COL_ROOT) * HID + o];
        g_B[slot][kpos(c) * HID + o] = __uint_as_float(f2tf32(v));
    } else if (b < 2 * GB_BLOCKS + 2 * H_BLOCKS) {
        int bb = b - 2 * GB_BLOCKS;
        int slot = (bb >= H_BLOCKS);
        const float* w1 = slot ? w1b : w1a;
        const float* b1 = slot ? b1b : b1a;
        for (int i = t; i < EDGE_DIM * EH; i += 256) sw[i] = w1[i];
        if (t < EH) sb[t] = b1[t];
        __syncthreads();
        int j  = t & 31;
        int e  = (bb - slot * H_BLOCKS) * 8 + (t >> 5);
        float acc = sb[j];
        #pragma unroll
        for (int d = 0; d < EDGE_DIM; d++)
            acc += ea[e * EDGE_DIM + d] * sw[d * EH + j];
        g_h[slot][e * EH + j] = fmaxf(acc, 0.0f);
    } else {
        int idx = (b - 2 * GB_BLOCKS - 2 * H_BLOCKS) * 256 + t;
        g_out[idx] = 0.0f;
    }
}

// =====================================================================
// Aggregation: CSR-by-dst, one block per node. Builds T row:
//   c = k*160+i   : inv * sum_e h_ek * x[src_e, i]
//   c = 5120+i    : inv * sum_e x[src_e, i]
//   c = 5280+i    : x[n, i]
// Written tf32-rounded, kpos-permuted. No atomics.
// =====================================================================
__global__ __launch_bounds__(256) void agg_kernel(const float* __restrict__ xin,
                                                  int xsel, int slot) {
    __shared__ float xs[HID];
    __shared__ float sh[EH];
    const float* __restrict__ X = (xsel < 0) ? xin : g_xb[xsel];
    int n = blockIdx.x;
    int t = threadIdx.x;
    int beg = g_csr_off[n];
    int end = g_csr_off[n + 1];
    float inv = 1.0f / fmaxf((float)(end - beg), 1.0f);

    float acc[20];
    int kk[20], ii[20];
    #pragma unroll
    for (int r = 0; r < 20; r++) {
        int c = t + 256 * r;          // < 5120
        kk[r] = c / HID;
        ii[r] = c % HID;
        acc[r] = 0.0f;
    }
    float acc2 = 0.0f;

    for (int j = beg; j < end; j++) {
        int e = g_csr_edge[j];
        int src = g_src[e];
        if (t < 40)
            ((float4*)xs)[t] = ((const float4*)(X + (size_t)src * HID))[t];
        else if (t >= 64 && t < 96)
            sh[t - 64] = g_h[slot][e * EH + (t - 64)];
        __syncthreads();
        #pragma unroll
        for (int r = 0; r < 20; r++)
            acc[r] += sh[kk[r]] * xs[ii[r]];
        if (t < HID) acc2 += xs[t];
        __syncthreads();
    }

    float* Tr = g_T + (size_t)n * NCOLS;
    #pragma unroll
    for (int r = 0; r < 20; r++)
        Tr[kpos(t + 256 * r)] = __uint_as_float(f2tf32(inv * acc[r]));
    if (t < HID) {
        Tr[kpos(COL_B2 + t)]   = __uint_as_float(f2tf32(inv * acc2));
        Tr[kpos(COL_ROOT + t)] = __uint_as_float(f2tf32(X[(size_t)n * HID + t]));
    }
}

// =====================================================================
// Split-K TF32 GEMM: g_out[2048,160] += T[2048,5440] @ B[5440,160]
// grid (9 splits, 16 m-tiles) = 144 CTAs (one wave).
// CTA: 256 thr, BM=128, BN=160, BK=32, warps 4(M)x2(N) -> 32x80 each.
// =====================================================================
#define TS_STRIDE 40
#define WS_STRIDE 164
#define TS_ELEMS (128 * TS_STRIDE)   // 5120
#define WS_ELEMS (32 * WS_STRIDE)    // 5248
#define GEMM_SMEM ((TS_ELEMS + WS_ELEMS) * 2 * 4)   // 82944 B
#define K_UNITS (NCOLS / 32)         // 170
#define SPLITS 9

__device__ __forceinline__ void mma_tf32(float* d, const uint32_t* a, const uint32_t* b) {
    asm volatile(
        "mma.sync.aligned.m16n8k8.row.col.f32.tf32.tf32.f32 "
        "{%0,%1,%2,%3}, {%4,%5,%6,%7}, {%8,%9}, {%0,%1,%2,%3};"
        : "+f"(d[0]), "+f"(d[1]), "+f"(d[2]), "+f"(d[3])
        : "r"(a[0]), "r"(a[1]), "r"(a[2]), "r"(a[3]), "r"(b[0]), "r"(b[1]));
}

__global__ __launch_bounds__(256, 1) void gemm_kernel(int wslot) {
    const float* __restrict__ W = g_B[wslot];

    extern __shared__ float smem[];
    float* Ts = smem;
    float* Ws = smem + 2 * TS_ELEMS;

    int tid  = threadIdx.x;
    int lane = tid & 31;
    int w    = tid >> 5;
    int wm   = w & 3;          // 4 warps in M
    int wn   = w >> 2;         // 2 warps in N
    int g    = lane >> 2;
    int tig  = lane & 3;

    int m0    = blockIdx.y * 128;
    int split = blockIdx.x;
    int u0    = split * 19;                 // splits 0..7: 19 units; split 8: 18
    int cnt   = (split == 8) ? (K_UNITS - 8 * 19) : 19;

    float acc[2][10][4];
    #pragma unroll
    for (int i = 0; i < 2; i++)
        #pragma unroll
        for (int j = 0; j < 10; j++)
            #pragma unroll
            for (int r = 0; r < 4; r++) acc[i][j][r] = 0.0f;

    auto stage = [&](int buf, int ku) {
        int k0 = ku * 32;
        float* td = Ts + buf * TS_ELEMS;
        float* wd = Ws + buf * WS_ELEMS;
        #pragma unroll
        for (int i = 0; i < 4; i++) {
            int s   = tid + 256 * i;
            int row = s >> 3;
            int col = (s & 7) * 4;
            uint32_t dst = (uint32_t)__cvta_generic_to_shared(&td[row * TS_STRIDE + col]);
            const float* src = g_T + (size_t)(m0 + row) * NCOLS + k0 + col;
            asm volatile("cp.async.cg.shared.global [%0], [%1], 16;"
                         :: "r"(dst), "l"(src));
        }
        #pragma unroll
        for (int i = 0; i < 5; i++) {
            int s   = tid + 256 * i;
            int row = s / 40;
            int col = (s % 40) * 4;
            uint32_t dst = (uint32_t)__cvta_generic_to_shared(&wd[row * WS_STRIDE + col]);
            const float* src = W + (size_t)(k0 + row) * HID + col;
            asm volatile("cp.async.cg.shared.global [%0], [%1], 16;"
                         :: "r"(dst), "l"(src));
        }
        asm volatile("cp.async.commit_group;");
    };

    stage(0, u0);

    for (int it = 0; it < cnt; it++) {
        if (it + 1 < cnt) {
            stage((it + 1) & 1, u0 + it + 1);
            asm volatile("cp.async.wait_group 1;");
        } else {
            asm volatile("cp.async.wait_group 0;");
        }
        __syncthreads();

        const uint32_t* ts = (const uint32_t*)(Ts + (it & 1) * TS_ELEMS);
        const uint32_t* ws = (const uint32_t*)(Ws + (it & 1) * WS_ELEMS);

        #pragma unroll
        for (int ks = 0; ks < 4; ks++) {
            int ck = ks * 8;
            uint32_t af[2][4];
            #pragma unroll
            for (int mt = 0; mt < 2; mt++) {
                int rb = wm * 32 + mt * 16;
                uint2 alo = *(const uint2*)&ts[(rb + g)     * TS_STRIDE + ck + 2 * tig];
                uint2 ahi = *(const uint2*)&ts[(rb + g + 8) * TS_STRIDE + ck + 2 * tig];
                af[mt][0] = alo.x;
                af[mt][1] = ahi.x;
                af[mt][2] = alo.y;
                af[mt][3] = ahi.y;
            }
            uint32_t bf[10][2];
            #pragma unroll
            for (int nt = 0; nt < 10; nt++) {
                int nc = wn * 80 + nt * 8 + g;
                bf[nt][0] = ws[(ck + 2 * tig)     * WS_STRIDE + nc];
                bf[nt][1] = ws[(ck + 2 * tig + 1) * WS_STRIDE + nc];
            }
            #pragma unroll
            for (int mt = 0; mt < 2; mt++)
                #pragma unroll
                for (int nt = 0; nt < 10; nt++)
                    mma_tf32(acc[mt][nt], af[mt], bf[nt]);
        }
        __syncthreads();
    }

    // split-K reduce via RED.F32
    #pragma unroll
    for (int mt = 0; mt < 2; mt++) {
        int row = m0 + wm * 32 + mt * 16 + g;
        #pragma unroll
        for (int nt = 0; nt < 10; nt++) {
            int col = wn * 80 + nt * 8 + 2 * tig;
            atomicAdd(&g_out[row * HID + col],           acc[mt][nt][0]);
            atomicAdd(&g_out[row * HID + col + 1],       acc[mt][nt][1]);
            atomicAdd(&g_out[(row + 8) * HID + col],     acc[mt][nt][2]);
            atomicAdd(&g_out[(row + 8) * HID + col + 1], acc[mt][nt][3]);
        }
    }
}

// =====================================================================
// Finalize: v = g_out + bias (+relu); write dest; re-zero g_out.
// =====================================================================
__global__ void final_kernel(const float* __restrict__ bias, int outsel,
                             float* __restrict__ dout, int relu) {
    int idx = blockIdx.x * blockDim.x + threadIdx.x;
    if (idx >= N_NODES * HID) return;
    int o = idx % HID;
    float v = g_out[idx] + bias[o];
    if (relu) v = fmaxf(v, 0.0f);
    g_out[idx] = 0.0f;
    if (outsel == 2) dout[idx] = v;
    else             g_xb[outsel][idx] = v;
}

// =====================================================================
// launch
// =====================================================================
extern "C" void kernel_launch(void* const* d_in, const int* in_sizes, int n_in,
                              void* d_out, int out_size) {
    const float* x       = (const float*)d_in[0];
    const float* ea      = (const float*)d_in[1];
    const float* w1_a    = (const float*)d_in[2];
    const float* b1_a    = (const float*)d_in[3];
    const float* w2_a    = (const float*)d_in[4];
    const float* b2_a    = (const float*)d_in[5];
    const float* root_a  = (const float*)d_in[6];
    const float* bias_a  = (const float*)d_in[7];
    const float* w1_b    = (const float*)d_in[8];
    const float* b1_b    = (const float*)d_in[9];
    const float* w2_b    = (const float*)d_in[10];
    const float* b2_b    = (const float*)d_in[11];
    const float* root_b  = (const float*)d_in[12];
    const float* bias_b  = (const float*)d_in[13];
    const void*  eidx    = d_in[14];
    float* out = (float*)d_out;

    static int smem_set = 0;
    if (!smem_set) {
        cudaFuncSetAttribute(gemm_kernel,
                             cudaFuncAttributeMaxDynamicSharedMemorySize, GEMM_SMEM);
        smem_set = 1;
    }

    prep_kernel<<<1, 1024>>>(eidx);
    params_kernel<<<2 * GB_BLOCKS + 2 * H_BLOCKS + Z_BLOCKS, 256>>>(
        w2_a, b2_a, root_a, w2_b, b2_b, root_b, ea, w1_a, b1_a, w1_b, b1_b);

    dim3 ggrid(SPLITS, N_NODES / 128);   // (9, 16)
    int fb = (N_NODES * HID + 255) / 256;

    // layer 0 (params a), relu
    agg_kernel<<<N_NODES, 256>>>(x, -1, 0);
    gemm_kernel<<<ggrid, 256, GEMM_SMEM>>>(0);
    final_kernel<<<fb, 256>>>(bias_a, 0, out, 1);

    // layer 1 (params b), relu
    agg_kernel<<<N_NODES, 256>>>(nullptr, 0, 1);
    gemm_kernel<<<ggrid, 256, GEMM_SMEM>>>(1);
    final_kernel<<<fb, 256>>>(bias_b, 1, out, 1);

    // layer 2 (params b), no relu -> d_out
    agg_kernel<<<N_NODES, 256>>>(nullptr, 1, 1);
    gemm_kernel<<<ggrid, 256, GEMM_SMEM>>>(1);
    final_kernel<<<fb, 256>>>(bias_b, 2, out, 0);
}